// round 3
// baseline (speedup 1.0000x reference)
#include <cuda_runtime.h>
#include <math.h>
#include <stdint.h>

// ---------------- problem constants (fixed shapes) ----------------
#define NTOK  16384            // 8 * 2048 tokens
#define CDIM  768
#define FDIM  3072
#define NEXP  8
#define NPAIR (NTOK * 2)       // top-2 routing -> 32768 (token,expert) pairs

// ---------------- scratch (static device arrays; no allocation) ----
__device__ int   g_count[NEXP];                      // tokens per expert
__device__ int   g_bucket[NEXP * NTOK];              // pair indices per expert
__device__ float g_wt[NPAIR];                        // combine weight per pair
__device__ float g_h[(size_t)NPAIR * FDIM];          // GELU(x@w1+b1) per pair (402 MB)

// ---------------- helpers ----------------
__device__ __forceinline__ float gelu_f(float x) {
    return 0.5f * x * (1.0f + erff(x * 0.70710678118654752440f));
}

__device__ __forceinline__ unsigned f2tf(float f) {
    unsigned u;
    asm("cvt.rna.tf32.f32 %0, %1;" : "=r"(u) : "f"(f));
    return u;
}

__device__ __forceinline__ void mma8(float c[4], const unsigned a[4], const unsigned b[2]) {
    asm volatile(
        "mma.sync.aligned.m16n8k8.row.col.f32.tf32.tf32.f32 "
        "{%0,%1,%2,%3},{%4,%5,%6,%7},{%8,%9},{%0,%1,%2,%3};"
        : "+f"(c[0]), "+f"(c[1]), "+f"(c[2]), "+f"(c[3])
        : "r"(a[0]), "r"(a[1]), "r"(a[2]), "r"(a[3]), "r"(b[0]), "r"(b[1]));
}

__device__ __forceinline__ void cp16(void* smem_dst, const void* gmem_src) {
    unsigned s = (unsigned)__cvta_generic_to_shared(smem_dst);
    asm volatile("cp.async.cg.shared.global [%0], [%1], 16;" :: "r"(s), "l"(gmem_src));
}
#define CP_COMMIT() asm volatile("cp.async.commit_group;")
#define CP_WAIT1()  asm volatile("cp.async.wait_group 1;")
#define CP_WAIT0()  asm volatile("cp.async.wait_group 0;")

// ---------------- kernel 0: zero output + counters ----------------
__global__ void init_kernel(float* __restrict__ out, int n) {
    int i = blockIdx.x * blockDim.x + threadIdx.x;
    if (i < NEXP) g_count[i] = 0;
    int stride = gridDim.x * blockDim.x;
    for (int j = i; j < n; j += stride) out[j] = 0.0f;
}

// ---------------- kernel 1: router (fp32 exact) ----------------
// 1 warp per token. logits = x @ router_w^T, top-2, 2-way softmax weights,
// scatter pair indices into per-expert buckets.
__global__ void router_kernel(const float* __restrict__ x, const float* __restrict__ rw) {
    __shared__ float srw[NEXP * CDIM];
    int tid = threadIdx.x;
    for (int j = tid; j < NEXP * CDIM; j += 256) srw[j] = rw[j];
    __syncthreads();

    int warp = tid >> 5, lane = tid & 31;
    int t = blockIdx.x * 8 + warp;   // grid = NTOK/8 blocks -> always in range

    float xv[24];
#pragma unroll
    for (int j = 0; j < 24; j++) xv[j] = x[(size_t)t * CDIM + lane + 32 * j];

    float logit[NEXP];
#pragma unroll
    for (int e = 0; e < NEXP; e++) {
        float s = 0.0f;
#pragma unroll
        for (int j = 0; j < 24; j++) s += xv[j] * srw[e * CDIM + lane + 32 * j];
#pragma unroll
        for (int o = 16; o > 0; o >>= 1) s += __shfl_xor_sync(0xffffffffu, s, o);
        logit[e] = s;
    }

    if (lane == 0) {
        int e0 = 0; float l0 = logit[0];
#pragma unroll
        for (int e = 1; e < NEXP; e++)
            if (logit[e] > l0) { l0 = logit[e]; e0 = e; }
        int e1 = (e0 == 0) ? 1 : 0; float l1 = logit[e1];
#pragma unroll
        for (int e = 0; e < NEXP; e++)
            if (e != e0 && logit[e] > l1) { l1 = logit[e]; e1 = e; }

        // normalized top-2 softmax == 2-way softmax over (l0, l1)
        float d  = expf(l1 - l0);          // <= 1, stable
        float w0 = 1.0f / (1.0f + d);
        float w1 = d / (1.0f + d);

        int p0 = 2 * t, p1 = 2 * t + 1;
        g_wt[p0] = w0;
        g_wt[p1] = w1;
        int pos0 = atomicAdd(&g_count[e0], 1);
        g_bucket[e0 * NTOK + pos0] = p0;
        int pos1 = atomicAdd(&g_count[e1], 1);
        g_bucket[e1 * NTOK + pos1] = p1;
    }
}

// ---------------- kernels 2/3: gathered TF32 GEMM ----------------
// PHASE 1: g_h[pair] = gelu(x[tok] @ w1[e] + b1[e])       (K=768,  N=3072)
// PHASE 2: out[tok] += w_pair * (g_h[pair] @ w2[e] + b2)  (K=3072, N=768)
#define BM   128
#define BN   128
#define BK   16
#define PADA 20     // BK + 4   -> conflict-free A frag loads
#define PADB 136    // BN + 8   -> conflict-free B frag loads

template <int PHASE>
__global__ void moe_gemm(const float* __restrict__ Xin,   // PHASE 1: x ; PHASE 2: unused
                         const float* __restrict__ W,     // w1 [E][C][F] or w2 [E][F][C]
                         const float* __restrict__ bias,  // b1 [E][F]   or b2 [E][C]
                         float* __restrict__ Out)         // PHASE 2: out [NTOK][C]
{
    constexpr int KD = (PHASE == 1) ? CDIM : FDIM;
    constexpr int ND = (PHASE == 1) ? FDIM : CDIM;
    constexpr int KT = KD / BK;

    const int e   = blockIdx.z;
    const int cnt = g_count[e];
    const int m0  = blockIdx.y * BM;
    if (m0 >= cnt) return;                 // over-provisioned static grid
    const int n0  = blockIdx.x * BN;

    __shared__ float As[2][BM][PADA];
    __shared__ float Bs[2][BK][PADB];
    __shared__ int   sPair[BM];
    __shared__ float sW[BM];

    const int tid = threadIdx.x;

    if (tid < BM) {
        int r  = m0 + tid;
        int pr = g_bucket[e * NTOK + min(r, cnt - 1)];   // clamp pad rows to a valid pair
        sPair[tid] = pr;
        if (PHASE == 2) sW[tid] = g_wt[pr];
    }
    __syncthreads();

    const float* Wb = W + (size_t)e * KD * ND;

    auto loadA = [&](int s, int k0) {
#pragma unroll
        for (int q = 0; q < 2; q++) {
            int idx = tid + q * 256;          // 0..511
            int row = idx >> 2;               // 0..127
            int ch  = idx & 3;                // 16B chunk within BK=16
            int pr  = sPair[row];
            const float* src;
            if constexpr (PHASE == 1)
                src = Xin + (size_t)(pr >> 1) * CDIM + k0 + ch * 4;
            else
                src = g_h + (size_t)pr * FDIM + k0 + ch * 4;
            cp16(&As[s][row][ch * 4], src);
        }
    };
    auto loadB = [&](int s, int k0) {
#pragma unroll
        for (int q = 0; q < 2; q++) {
            int idx = tid + q * 256;          // 0..511
            int row = idx >> 5;               // 0..15
            int ch  = idx & 31;               // 16B chunk within BN=128
            cp16(&Bs[s][row][ch * 4], Wb + (size_t)(k0 + row) * ND + n0 + ch * 4);
        }
    };

    const int warp = tid >> 5, lane = tid & 31;
    const int wm = warp >> 2, wn = warp & 3;      // 2 x 4 warp grid -> 64 x 32 warp tile
    const int gid = lane >> 2, tig = lane & 3;

    float acc[4][4][4];
#pragma unroll
    for (int i = 0; i < 4; i++)
#pragma unroll
        for (int j = 0; j < 4; j++)
#pragma unroll
            for (int r = 0; r < 4; r++) acc[i][j][r] = 0.0f;

    loadA(0, 0); loadB(0, 0); CP_COMMIT();

    for (int kt = 0; kt < KT; kt++) {
        const int s = kt & 1;
        if (kt + 1 < KT) {
            loadA(s ^ 1, (kt + 1) * BK);
            loadB(s ^ 1, (kt + 1) * BK);
            CP_COMMIT();
            CP_WAIT1();                 // current stage s complete, next in flight
        } else {
            CP_WAIT0();
        }
        __syncthreads();

#pragma unroll
        for (int ks = 0; ks < BK / 8; ks++) {
            const int kk = ks * 8;
            unsigned a[4][4], b[4][2];
#pragma unroll
            for (int mi = 0; mi < 4; mi++) {
                int r = wm * 64 + mi * 16 + gid;
                a[mi][0] = f2tf(As[s][r][kk + tig]);
                a[mi][1] = f2tf(As[s][r + 8][kk + tig]);
                a[mi][2] = f2tf(As[s][r][kk + tig + 4]);
                a[mi][3] = f2tf(As[s][r + 8][kk + tig + 4]);
            }
#pragma unroll
            for (int ni = 0; ni < 4; ni++) {
                int c = wn * 32 + ni * 8 + gid;
                b[ni][0] = f2tf(Bs[s][kk + tig][c]);
                b[ni][1] = f2tf(Bs[s][kk + tig + 4][c]);
            }
#pragma unroll
            for (int mi = 0; mi < 4; mi++)
#pragma unroll
                for (int ni = 0; ni < 4; ni++)
                    mma8(acc[mi][ni], a[mi], b[ni]);
        }
        __syncthreads();   // protect stage s before it is overwritten next iter
    }

    // ---------------- epilogue ----------------
    const float* bptr = bias + (size_t)e * ND;
#pragma unroll
    for (int mi = 0; mi < 4; mi++) {
#pragma unroll
        for (int half = 0; half < 2; half++) {
            int rl = wm * 64 + mi * 16 + gid + half * 8;
            if (m0 + rl < cnt) {
                int pr = sPair[rl];
                if constexpr (PHASE == 1) {
                    float* dst = g_h + (size_t)pr * FDIM;
#pragma unroll
                    for (int ni = 0; ni < 4; ni++) {
                        int n = n0 + wn * 32 + ni * 8 + 2 * tig;
                        float v0 = gelu_f(acc[mi][ni][half * 2 + 0] + bptr[n]);
                        float v1 = gelu_f(acc[mi][ni][half * 2 + 1] + bptr[n + 1]);
                        *reinterpret_cast<float2*>(dst + n) = make_float2(v0, v1);
                    }
                } else {
                    float wgt  = sW[rl];
                    float* dst = Out + (size_t)(pr >> 1) * CDIM;
#pragma unroll
                    for (int ni = 0; ni < 4; ni++) {
                        int n = n0 + wn * 32 + ni * 8 + 2 * tig;
                        // exactly 2 commutative adds per element -> deterministic
                        atomicAdd(dst + n,     wgt * (acc[mi][ni][half * 2 + 0] + bptr[n]));
                        atomicAdd(dst + n + 1, wgt * (acc[mi][ni][half * 2 + 1] + bptr[n + 1]));
                    }
                }
            }
        }
    }
}

// ---------------- launch ----------------
extern "C" void kernel_launch(void* const* d_in, const int* in_sizes, int n_in,
                              void* d_out, int out_size) {
    (void)in_sizes; (void)n_in;
    const float* x  = (const float*)d_in[0];
    const float* rw = (const float*)d_in[1];
    const float* w1 = (const float*)d_in[2];
    const float* b1 = (const float*)d_in[3];
    const float* w2 = (const float*)d_in[4];
    const float* b2 = (const float*)d_in[5];
    float* out = (float*)d_out;

    init_kernel<<<2048, 256>>>(out, out_size);
    router_kernel<<<NTOK / 8, 256>>>(x, rw);
    moe_gemm<1><<<dim3(FDIM / BN, NTOK / BM, NEXP), 256>>>(x, w1, b1, nullptr);
    moe_gemm<2><<<dim3(CDIM / BN, NTOK / BM, NEXP), 256>>>(nullptr, w2, b2, out);
}

// round 5
// speedup vs baseline: 2.2632x; 2.2632x over previous
#include <cuda_runtime.h>
#include <cuda_fp16.h>
#include <math.h>
#include <stdint.h>

// ---------------- problem constants ----------------
#define NTOK  16384
#define CDIM  768
#define FDIM  3072
#define NEXP  8
#define NPAIR (NTOK * 2)

// ---------------- scratch (static device arrays) ----------------
__device__ int    g_count[NEXP];
__device__ int    g_bucket[NEXP * NTOK];
__device__ float  g_wt[NPAIR];
__device__ __half g_xh[(size_t)NTOK * CDIM];          // x in fp16
__device__ __half g_w1t[(size_t)NEXP * FDIM * CDIM];  // w1^T fp16 [E][F][C] (N-major rows, K contig)
__device__ __half g_w2t[(size_t)NEXP * CDIM * FDIM];  // w2^T fp16 [E][C][F]
__device__ __half g_h[(size_t)NPAIR * FDIM];          // gelu(x@w1+b1) fp16
__device__ float  g_y[(size_t)NPAIR * CDIM];          // w*(h@w2+b2) per pair

// ---------------- helpers ----------------
__device__ __forceinline__ float gelu_f(float x) {
    return 0.5f * x * (1.0f + erff(x * 0.70710678118654752440f));
}
__device__ __forceinline__ uint32_t sw128(uint32_t o) { return o ^ ((o >> 3) & 0x70); }

__device__ __forceinline__ void cp16s(uint32_t saddr, const void* g) {
    asm volatile("cp.async.cg.shared.global [%0], [%1], 16;" :: "r"(saddr), "l"(g));
}

__device__ __forceinline__ void ldm_x4(uint32_t r[4], uint32_t addr) {
    asm volatile("ldmatrix.sync.aligned.m8n8.x4.shared.b16 {%0,%1,%2,%3}, [%4];"
                 : "=r"(r[0]), "=r"(r[1]), "=r"(r[2]), "=r"(r[3]) : "r"(addr));
}

__device__ __forceinline__ void mma16816(float c[4], const uint32_t a[4], const uint32_t* b) {
    asm volatile(
        "mma.sync.aligned.m16n8k16.row.col.f32.f16.f16.f32 "
        "{%0,%1,%2,%3},{%4,%5,%6,%7},{%8,%9},{%0,%1,%2,%3};"
        : "+f"(c[0]), "+f"(c[1]), "+f"(c[2]), "+f"(c[3])
        : "r"(a[0]), "r"(a[1]), "r"(a[2]), "r"(a[3]), "r"(b[0]), "r"(b[1]));
}

// ---------------- kernel: init (zero expert counters) ----------------
__global__ void init_kernel() {
    if (threadIdx.x < NEXP) g_count[threadIdx.x] = 0;
}

// ---------------- kernel: convert x -> fp16 ----------------
__global__ void convert_x(const float* __restrict__ x) {
    const float4* x4 = (const float4*)x;
    uint2* o = (uint2*)g_xh;
    int n4 = NTOK * CDIM / 4;
    for (int j = blockIdx.x * blockDim.x + threadIdx.x; j < n4; j += gridDim.x * blockDim.x) {
        float4 v = x4[j];
        __half2 a = __floats2half2_rn(v.x, v.y);
        __half2 b = __floats2half2_rn(v.z, v.w);
        o[j] = make_uint2(*(uint32_t*)&a, *(uint32_t*)&b);
    }
}

// ---------------- kernel: transpose + convert weights ----------------
// in: [E][R][S] fp32 -> out: [E][S][R] fp16
template <int WSEL>
__global__ void transpose_h(const float* __restrict__ in, int R, int S) {
    __half* out = (WSEL == 1) ? g_w1t : g_w2t;
    __shared__ float tile[32][33];
    int e = blockIdx.z;
    const float* I = in + (size_t)e * R * S;
    __half* O = out + (size_t)e * R * S;
    int s0 = blockIdx.x * 32, r0 = blockIdx.y * 32;
    int tx = threadIdx.x, ty = threadIdx.y;
#pragma unroll
    for (int k = 0; k < 4; k++)
        tile[ty + 8 * k][tx] = I[(size_t)(r0 + ty + 8 * k) * S + s0 + tx];
    __syncthreads();
#pragma unroll
    for (int k = 0; k < 4; k++)
        O[(size_t)(s0 + ty + 8 * k) * R + r0 + tx] = __float2half(tile[tx][ty + 8 * k]);
}

// ---------------- kernel: router (fp32 exact, proven R2) ----------------
__global__ void router_kernel(const float* __restrict__ x, const float* __restrict__ rw) {
    __shared__ float srw[NEXP * CDIM];
    int tid = threadIdx.x;
    for (int j = tid; j < NEXP * CDIM; j += 256) srw[j] = rw[j];
    __syncthreads();

    int warp = tid >> 5, lane = tid & 31;
    int t = blockIdx.x * 8 + warp;

    float xv[24];
#pragma unroll
    for (int j = 0; j < 24; j++) xv[j] = x[(size_t)t * CDIM + lane + 32 * j];

    float logit[NEXP];
#pragma unroll
    for (int e = 0; e < NEXP; e++) {
        float s = 0.0f;
#pragma unroll
        for (int j = 0; j < 24; j++) s += xv[j] * srw[e * CDIM + lane + 32 * j];
#pragma unroll
        for (int o = 16; o > 0; o >>= 1) s += __shfl_xor_sync(0xffffffffu, s, o);
        logit[e] = s;
    }

    if (lane == 0) {
        int e0 = 0; float l0 = logit[0];
#pragma unroll
        for (int e = 1; e < NEXP; e++)
            if (logit[e] > l0) { l0 = logit[e]; e0 = e; }
        int e1 = (e0 == 0) ? 1 : 0; float l1 = logit[e1];
#pragma unroll
        for (int e = 0; e < NEXP; e++)
            if (e != e0 && logit[e] > l1) { l1 = logit[e]; e1 = e; }

        float d = expf(l1 - l0);
        float w0 = 1.0f / (1.0f + d);
        float w1 = d / (1.0f + d);

        int p0 = 2 * t, p1 = 2 * t + 1;
        g_wt[p0] = w0;
        g_wt[p1] = w1;
        int pos0 = atomicAdd(&g_count[e0], 1);
        g_bucket[e0 * NTOK + pos0] = p0;
        int pos1 = atomicAdd(&g_count[e1], 1);
        g_bucket[e1 * NTOK + pos1] = p1;
    }
}

// ---------------- fp16 HMMA MoE GEMM ----------------
// PHASE 1: g_h[pair] = gelu(x[tok] @ w1[e] + b1[e])       (K=768,  N=3072)
// PHASE 2: g_y[pair] = w_pair * (g_h[pair] @ w2[e] + b2)  (K=3072, N=768)
//
// A smem: [128 m-rows][64 halves = 128B], SW128 swizzled, K-major
// B smem: [128 n-rows][64 halves = 128B], SW128 swizzled, K-major (weights pre-transposed)
#define BM   128
#define BN   128
#define BKH  64                           // halves of K per chunk (128B rows)
#define A_BYTES (BM * 128)
#define B_BYTES (BN * 128)
#define STAGE_BYTES (A_BYTES + B_BYTES)   // 32768
#define SMEM_DYN (2 * STAGE_BYTES + 1024) // 2 stages + align slack

template <int PHASE>
__global__ void __launch_bounds__(256, 2) moe_gemm(const float* __restrict__ bias) {
    constexpr int KD = (PHASE == 1) ? CDIM : FDIM;
    constexpr int ND = (PHASE == 1) ? FDIM : CDIM;
    constexpr int KT = KD / BKH;          // 12 or 48

    const int e   = blockIdx.z;
    const int cnt = g_count[e];
    const int m0  = blockIdx.y * BM;
    if (m0 >= cnt) return;
    const int n0  = blockIdx.x * BN;

    extern __shared__ char dsm[];
    uint32_t sb0;
    asm("{ .reg .u64 t; cvta.to.shared.u64 t, %1; cvt.u32.u64 %0, t; }" : "=r"(sb0) : "l"(dsm));
    const uint32_t sbase = (sb0 + 1023) & ~1023u;   // 1KB align for clean swizzle lines

    __shared__ int   sPair[BM];
    __shared__ float sW[BM];

    const int tid  = threadIdx.x;
    const int wid  = tid >> 5;
    const int lane = tid & 31;

    if (tid < BM) {
        int pr = g_bucket[e * NTOK + min(m0 + tid, cnt - 1)];
        sPair[tid] = pr;
        sW[tid] = g_wt[pr];
    }
    __syncthreads();

    const __half* Ag = (PHASE == 1) ? g_xh : g_h;
    const __half* Wt = (PHASE == 1) ? g_w1t : g_w2t;
    const __half* We = Wt + (size_t)e * KD * ND + (size_t)n0 * KD;

    auto load_chunk = [&](int kt, int s) {
        const uint32_t ab = sbase + s * STAGE_BYTES;
        const uint32_t bb = ab + A_BYTES;
        const int koff = kt * BKH;
#pragma unroll
        for (int q = 0; q < 4; q++) {                 // A: 1024 x 16B
            int idx = tid + q * 256;
            int row = idx >> 3, ch = idx & 7;
            int pr = sPair[row];
            const __half* src = Ag +
                ((PHASE == 1) ? (size_t)(pr >> 1) * CDIM : (size_t)pr * FDIM) + koff + ch * 8;
            cp16s(ab + sw128(row * 128 + ch * 16), src);
        }
#pragma unroll
        for (int q = 0; q < 4; q++) {                 // B: 1024 x 16B
            int idx = tid + q * 256;
            int row = idx >> 3, ch = idx & 7;
            cp16s(bb + sw128(row * 128 + ch * 16), We + (size_t)row * KD + koff + ch * 8);
        }
        asm volatile("cp.async.commit_group;");
    };

    // ---- per-thread ldmatrix address precompute ----
    const int wm = wid >> 2, wn = wid & 3;            // 2x4 warp grid, warp tile 64x32
    const int ahi = lane >> 4;                        // A chunk-hi bit
    const int bhi = (lane >> 3) & 1;                  // B chunk-hi bit
    uint32_t arel[4]; int axr[4];
#pragma unroll
    for (int mi = 0; mi < 4; mi++) {
        int r = wm * 64 + mi * 16 + (lane & 15);
        arel[mi] = r * 128;
        axr[mi] = r & 7;
    }
    uint32_t brel[2]; int bxr[2];
#pragma unroll
    for (int nj = 0; nj < 2; nj++) {
        int r = wn * 32 + nj * 16 + ((lane >> 4) << 3) + (lane & 7);
        brel[nj] = r * 128;
        bxr[nj] = r & 7;
    }

    float acc[4][4][4];
#pragma unroll
    for (int i = 0; i < 4; i++)
#pragma unroll
        for (int j = 0; j < 4; j++)
#pragma unroll
            for (int r = 0; r < 4; r++) acc[i][j][r] = 0.0f;

    load_chunk(0, 0);

#pragma unroll 1
    for (int kt = 0; kt < KT; kt++) {
        const int s = kt & 1;
        if (kt + 1 < KT) {
            load_chunk(kt + 1, s ^ 1);
            asm volatile("cp.async.wait_group 1;");
        } else {
            asm volatile("cp.async.wait_group 0;");
        }
        __syncthreads();

        const uint32_t ab = sbase + s * STAGE_BYTES;
        const uint32_t bb = ab + A_BYTES;
#pragma unroll
        for (int ks = 0; ks < 4; ks++) {
            uint32_t a[4][4], b[2][4];
#pragma unroll
            for (int mi = 0; mi < 4; mi++)
                ldm_x4(a[mi], ab + arel[mi] + ((uint32_t)((ks * 2 + ahi) ^ axr[mi]) << 4));
#pragma unroll
            for (int nj = 0; nj < 2; nj++)
                ldm_x4(b[nj], bb + brel[nj] + ((uint32_t)((ks * 2 + bhi) ^ bxr[nj]) << 4));
#pragma unroll
            for (int mi = 0; mi < 4; mi++)
#pragma unroll
                for (int ni = 0; ni < 4; ni++)
                    mma16816(acc[mi][ni], a[mi], &b[ni >> 1][(ni & 1) * 2]);
        }
        __syncthreads();
    }

    // ---------------- epilogue ----------------
    const int gid = lane >> 2, tig = lane & 3;
    const float* bptr = bias + (size_t)e * ND;
#pragma unroll
    for (int mi = 0; mi < 4; mi++) {
#pragma unroll
        for (int half = 0; half < 2; half++) {
            int rl = wm * 64 + mi * 16 + gid + half * 8;
            if (m0 + rl < cnt) {
                int pr = sPair[rl];
                if (PHASE == 1) {
                    __half* dst = g_h + (size_t)pr * FDIM;
#pragma unroll
                    for (int ni = 0; ni < 4; ni++) {
                        int n = n0 + wn * 32 + ni * 8 + 2 * tig;
                        float v0 = gelu_f(acc[mi][ni][half * 2 + 0] + bptr[n]);
                        float v1 = gelu_f(acc[mi][ni][half * 2 + 1] + bptr[n + 1]);
                        __half2 h2 = __floats2half2_rn(v0, v1);
                        *reinterpret_cast<__half2*>(dst + n) = h2;
                    }
                } else {
                    float wgt  = sW[rl];
                    float* dst = g_y + (size_t)pr * CDIM;
#pragma unroll
                    for (int ni = 0; ni < 4; ni++) {
                        int n = n0 + wn * 32 + ni * 8 + 2 * tig;
                        float2 v;
                        v.x = wgt * (acc[mi][ni][half * 2 + 0] + bptr[n]);
                        v.y = wgt * (acc[mi][ni][half * 2 + 1] + bptr[n + 1]);
                        *reinterpret_cast<float2*>(dst + n) = v;
                    }
                }
            }
        }
    }
}

// ---------------- kernel: combine pairs -> out (epilogue already weighted) --
__global__ void combine_kernel(float* __restrict__ out) {
    int i = blockIdx.x * blockDim.x + threadIdx.x;   // over NTOK * CDIM/4
    const int n4 = NTOK * (CDIM / 4);
    if (i >= n4) return;
    int t = i / (CDIM / 4), c = i % (CDIM / 4);
    float4 a = ((const float4*)(g_y + (size_t)(2 * t) * CDIM))[c];
    float4 b = ((const float4*)(g_y + (size_t)(2 * t + 1) * CDIM))[c];
    float4 r;
    r.x = a.x + b.x;
    r.y = a.y + b.y;
    r.z = a.z + b.z;
    r.w = a.w + b.w;
    ((float4*)out)[i] = r;
}

// ---------------- launch ----------------
extern "C" void kernel_launch(void* const* d_in, const int* in_sizes, int n_in,
                              void* d_out, int out_size) {
    (void)in_sizes; (void)n_in; (void)out_size;
    const float* x  = (const float*)d_in[0];
    const float* rw = (const float*)d_in[1];
    const float* w1 = (const float*)d_in[2];
    const float* b1 = (const float*)d_in[3];
    const float* w2 = (const float*)d_in[4];
    const float* b2 = (const float*)d_in[5];
    float* out = (float*)d_out;

    cudaFuncSetAttribute(moe_gemm<1>, cudaFuncAttributeMaxDynamicSharedMemorySize, SMEM_DYN);
    cudaFuncSetAttribute(moe_gemm<2>, cudaFuncAttributeMaxDynamicSharedMemorySize, SMEM_DYN);

    init_kernel<<<1, 32>>>();
    convert_x<<<2048, 256>>>(x);
    transpose_h<1><<<dim3(FDIM / 32, CDIM / 32, NEXP), dim3(32, 8)>>>(w1, CDIM, FDIM);
    transpose_h<2><<<dim3(CDIM / 32, FDIM / 32, NEXP), dim3(32, 8)>>>(w2, FDIM, CDIM);
    router_kernel<<<NTOK / 8, 256>>>(x, rw);

    moe_gemm<1><<<dim3(FDIM / BN, NTOK / BM, NEXP), 256, SMEM_DYN>>>(b1);
    moe_gemm<2><<<dim3(CDIM / BN, NTOK / BM, NEXP), 256, SMEM_DYN>>>(b2);

    combine_kernel<<<(NTOK * (CDIM / 4) + 255) / 256, 256>>>(out);
}

// round 6
// speedup vs baseline: 2.4492x; 1.0822x over previous
#include <cuda_runtime.h>
#include <cuda_fp16.h>
#include <math.h>
#include <stdint.h>

// ---------------- problem constants ----------------
#define NTOK  16384
#define CDIM  768
#define FDIM  3072
#define NEXP  8
#define NPAIR (NTOK * 2)

// ---------------- scratch (static device arrays) ----------------
__device__ int    g_count[NEXP];
__device__ int    g_bucket[NEXP * NTOK];
__device__ float  g_wt[NPAIR];
__device__ __half g_xh[(size_t)NTOK * CDIM];          // x in fp16
__device__ __half g_w1t[(size_t)NEXP * FDIM * CDIM];  // w1^T fp16 [E][F][C] (K contig)
__device__ __half g_w2t[(size_t)NEXP * CDIM * FDIM];  // w2^T fp16 [E][C][F]
__device__ __half g_h[(size_t)NPAIR * FDIM];          // gelu(x@w1+b1) fp16
__device__ float  g_y[(size_t)NPAIR * CDIM];          // w*(h@w2+b2) per pair

// ---------------- helpers ----------------
__device__ __forceinline__ float gelu_f(float x) {
    return 0.5f * x * (1.0f + erff(x * 0.70710678118654752440f));
}
__device__ __forceinline__ uint32_t sw128(uint32_t o) { return o ^ ((o >> 3) & 0x70); }

__device__ __forceinline__ void cp16s(uint32_t saddr, const void* g) {
    asm volatile("cp.async.cg.shared.global [%0], [%1], 16;" :: "r"(saddr), "l"(g));
}

__device__ __forceinline__ void ldm_x4(uint32_t r[4], uint32_t addr) {
    asm volatile("ldmatrix.sync.aligned.m8n8.x4.shared.b16 {%0,%1,%2,%3}, [%4];"
                 : "=r"(r[0]), "=r"(r[1]), "=r"(r[2]), "=r"(r[3]) : "r"(addr));
}

__device__ __forceinline__ void mma16816(float c[4], const uint32_t a[4], const uint32_t* b) {
    asm volatile(
        "mma.sync.aligned.m16n8k16.row.col.f32.f16.f16.f32 "
        "{%0,%1,%2,%3},{%4,%5,%6,%7},{%8,%9},{%0,%1,%2,%3};"
        : "+f"(c[0]), "+f"(c[1]), "+f"(c[2]), "+f"(c[3])
        : "r"(a[0]), "r"(a[1]), "r"(a[2]), "r"(a[3]), "r"(b[0]), "r"(b[1]));
}

// ---------------- kernel: init ----------------
__global__ void init_kernel() {
    if (threadIdx.x < NEXP) g_count[threadIdx.x] = 0;
}

// ---------------- kernel: router + fused x->fp16 conversion ----------------
__global__ void router_kernel(const float* __restrict__ x, const float* __restrict__ rw) {
    __shared__ float srw[NEXP * CDIM];
    int tid = threadIdx.x;
    for (int j = tid; j < NEXP * CDIM; j += 256) srw[j] = rw[j];
    __syncthreads();

    int warp = tid >> 5, lane = tid & 31;
    int t = blockIdx.x * 8 + warp;

    float xv[24];
#pragma unroll
    for (int j = 0; j < 24; j++) xv[j] = x[(size_t)t * CDIM + lane + 32 * j];

    // fused conversion: write x row as fp16
#pragma unroll
    for (int j = 0; j < 24; j++)
        g_xh[(size_t)t * CDIM + lane + 32 * j] = __float2half(xv[j]);

    float logit[NEXP];
#pragma unroll
    for (int e = 0; e < NEXP; e++) {
        float s = 0.0f;
#pragma unroll
        for (int j = 0; j < 24; j++) s += xv[j] * srw[e * CDIM + lane + 32 * j];
#pragma unroll
        for (int o = 16; o > 0; o >>= 1) s += __shfl_xor_sync(0xffffffffu, s, o);
        logit[e] = s;
    }

    if (lane == 0) {
        int e0 = 0; float l0 = logit[0];
#pragma unroll
        for (int e = 1; e < NEXP; e++)
            if (logit[e] > l0) { l0 = logit[e]; e0 = e; }
        int e1 = (e0 == 0) ? 1 : 0; float l1 = logit[e1];
#pragma unroll
        for (int e = 0; e < NEXP; e++)
            if (e != e0 && logit[e] > l1) { l1 = logit[e]; e1 = e; }

        float d = expf(l1 - l0);
        float w0 = 1.0f / (1.0f + d);
        float w1 = d / (1.0f + d);

        int p0 = 2 * t, p1 = 2 * t + 1;
        g_wt[p0] = w0;
        g_wt[p1] = w1;
        int pos0 = atomicAdd(&g_count[e0], 1);
        g_bucket[e0 * NTOK + pos0] = p0;
        int pos1 = atomicAdd(&g_count[e1], 1);
        g_bucket[e1 * NTOK + pos1] = p1;
    }
}

// ---------------- kernel: transpose + convert weights (half2 stores) ------
// in: [E][R][S] fp32 -> out: [E][S][R] fp16.  Tile: 64 r-rows x 32 s-cols.
template <int WSEL>
__global__ void transpose_h(const float* __restrict__ in, int R, int S) {
    __half* out = (WSEL == 1) ? g_w1t : g_w2t;
    __shared__ float tile[64][33];
    int e = blockIdx.z;
    const float* I = in + (size_t)e * R * S;
    __half* O = out + (size_t)e * R * S;
    int s0 = blockIdx.x * 32, r0 = blockIdx.y * 64;
    int tx = threadIdx.x, ty = threadIdx.y;   // block (32, 8)
#pragma unroll
    for (int k = 0; k < 8; k++)
        tile[ty + 8 * k][tx] = I[(size_t)(r0 + ty + 8 * k) * S + s0 + tx];
    __syncthreads();
#pragma unroll
    for (int k = 0; k < 4; k++) {
        int sy = ty + 8 * k;                  // 0..31
        __half2 h2 = __floats2half2_rn(tile[2 * tx][sy], tile[2 * tx + 1][sy]);
        *reinterpret_cast<__half2*>(O + (size_t)(s0 + sy) * R + r0 + 2 * tx) = h2;
    }
}

// ---------------- fp16 HMMA MoE GEMM (3-stage, 1 sync/iter) ----------------
// PHASE 1: g_h[pair] = gelu(x[tok] @ w1[e] + b1[e])       (K=768,  N=3072)
// PHASE 2: g_y[pair] = w_pair * (g_h[pair] @ w2[e] + b2)  (K=3072, N=768)
#define BM   128
#define BN   128
#define BKH  64                           // halves of K per chunk (128B rows)
#define NST  3
#define A_BYTES (BM * 128)
#define B_BYTES (BN * 128)
#define STAGE_BYTES (A_BYTES + B_BYTES)   // 32768
#define SMEM_DYN (NST * STAGE_BYTES + 1024)

template <int PHASE>
__global__ void __launch_bounds__(256, 2) moe_gemm(const float* __restrict__ bias) {
    constexpr int KD = (PHASE == 1) ? CDIM : FDIM;
    constexpr int ND = (PHASE == 1) ? FDIM : CDIM;
    constexpr int KT = KD / BKH;          // 12 or 48

    const int e   = blockIdx.z;
    const int cnt = g_count[e];
    const int m0  = blockIdx.x * BM;      // raster swap: x = m-tile (B reuse in-wave)
    if (m0 >= cnt) return;
    const int n0  = blockIdx.y * BN;

    extern __shared__ char dsm[];
    uint32_t sb0;
    asm("{ .reg .u64 t; cvta.to.shared.u64 t, %1; cvt.u32.u64 %0, t; }" : "=r"(sb0) : "l"(dsm));
    const uint32_t sbase = (sb0 + 1023) & ~1023u;

    __shared__ int   sPair[BM];
    __shared__ float sW[BM];

    const int tid  = threadIdx.x;
    const int wid  = tid >> 5;
    const int lane = tid & 31;

    if (tid < BM) {
        int pr = g_bucket[e * NTOK + min(m0 + tid, cnt - 1)];
        sPair[tid] = pr;
        sW[tid] = g_wt[pr];
    }
    __syncthreads();

    const __half* Ag = (PHASE == 1) ? g_xh : g_h;
    const __half* We = ((PHASE == 1) ? g_w1t : g_w2t)
                       + (size_t)e * KD * ND + (size_t)n0 * KD;

    // ---- per-thread precomputed copy sources / swizzled dests ----
    const int crow = tid >> 3, cch = tid & 7;          // 32 rows per pass, 8x16B per row
    const __half* aSrc[4]; const __half* bSrc[4];
    uint32_t aDst[4], bDst[4];
#pragma unroll
    for (int q = 0; q < 4; q++) {
        int r = crow + q * 32;
        int pr = sPair[r];
        aSrc[q] = Ag + ((PHASE == 1) ? (size_t)(pr >> 1) * CDIM : (size_t)pr * FDIM) + cch * 8;
        bSrc[q] = We + (size_t)r * KD + cch * 8;
        aDst[q] = sw128((uint32_t)(r * 128 + cch * 16));
        bDst[q] = sw128((uint32_t)(r * 128 + cch * 16)) + A_BYTES;
    }

    auto load_chunk = [&](int kt) {
        const uint32_t base = sbase + (kt % NST) * STAGE_BYTES;
        const int koff = kt * BKH;
#pragma unroll
        for (int q = 0; q < 4; q++) cp16s(base + aDst[q], aSrc[q] + koff);
#pragma unroll
        for (int q = 0; q < 4; q++) cp16s(base + bDst[q], bSrc[q] + koff);
        asm volatile("cp.async.commit_group;");
    };

    // ---- per-thread ldmatrix address precompute ----
    const int wm = wid >> 2, wn = wid & 3;             // 2x4 warp grid, warp tile 64x32
    const int ahi = lane >> 4;
    const int bhi = (lane >> 3) & 1;
    uint32_t arel[4]; int axr[4];
#pragma unroll
    for (int mi = 0; mi < 4; mi++) {
        int r = wm * 64 + mi * 16 + (lane & 15);
        arel[mi] = r * 128;
        axr[mi] = r & 7;
    }
    uint32_t brel[2]; int bxr[2];
#pragma unroll
    for (int nj = 0; nj < 2; nj++) {
        int r = wn * 32 + nj * 16 + ((lane >> 4) << 3) + (lane & 7);
        brel[nj] = r * 128;
        bxr[nj] = r & 7;
    }

    float acc[4][4][4];
#pragma unroll
    for (int i = 0; i < 4; i++)
#pragma unroll
        for (int j = 0; j < 4; j++)
#pragma unroll
            for (int r = 0; r < 4; r++) acc[i][j][r] = 0.0f;

    load_chunk(0);
    load_chunk(1);

#pragma unroll 1
    for (int kt = 0; kt < KT; kt++) {
        if (kt + 2 < KT) asm volatile("cp.async.wait_group 1;");
        else             asm volatile("cp.async.wait_group 0;");
        __syncthreads();
        if (kt + 2 < KT) load_chunk(kt + 2);   // after barrier: stage (kt+2)%3 free

        const uint32_t ab = sbase + (kt % NST) * STAGE_BYTES;
        const uint32_t bb = ab + A_BYTES;
#pragma unroll
        for (int ks = 0; ks < 4; ks++) {
            uint32_t a[4][4], b[2][4];
#pragma unroll
            for (int mi = 0; mi < 4; mi++)
                ldm_x4(a[mi], ab + arel[mi] + ((uint32_t)((ks * 2 + ahi) ^ axr[mi]) << 4));
#pragma unroll
            for (int nj = 0; nj < 2; nj++)
                ldm_x4(b[nj], bb + brel[nj] + ((uint32_t)((ks * 2 + bhi) ^ bxr[nj]) << 4));
#pragma unroll
            for (int mi = 0; mi < 4; mi++)
#pragma unroll
                for (int ni = 0; ni < 4; ni++)
                    mma16816(acc[mi][ni], a[mi], &b[ni >> 1][(ni & 1) * 2]);
        }
    }

    // ---------------- epilogue ----------------
    const int gid = lane >> 2, tig = lane & 3;
    const float* bptr = bias + (size_t)e * ND;
#pragma unroll
    for (int mi = 0; mi < 4; mi++) {
#pragma unroll
        for (int half = 0; half < 2; half++) {
            int rl = wm * 64 + mi * 16 + gid + half * 8;
            if (m0 + rl < cnt) {
                int pr = sPair[rl];
                if (PHASE == 1) {
                    __half* dst = g_h + (size_t)pr * FDIM;
#pragma unroll
                    for (int ni = 0; ni < 4; ni++) {
                        int n = n0 + wn * 32 + ni * 8 + 2 * tig;
                        float v0 = gelu_f(acc[mi][ni][half * 2 + 0] + bptr[n]);
                        float v1 = gelu_f(acc[mi][ni][half * 2 + 1] + bptr[n + 1]);
                        *reinterpret_cast<__half2*>(dst + n) = __floats2half2_rn(v0, v1);
                    }
                } else {
                    float wgt  = sW[rl];
                    float* dst = g_y + (size_t)pr * CDIM;
#pragma unroll
                    for (int ni = 0; ni < 4; ni++) {
                        int n = n0 + wn * 32 + ni * 8 + 2 * tig;
                        float2 v;
                        v.x = wgt * (acc[mi][ni][half * 2 + 0] + bptr[n]);
                        v.y = wgt * (acc[mi][ni][half * 2 + 1] + bptr[n + 1]);
                        *reinterpret_cast<float2*>(dst + n) = v;
                    }
                }
            }
        }
    }
}

// ---------------- kernel: combine pairs -> out ----------------
__global__ void combine_kernel(float* __restrict__ out) {
    int i = blockIdx.x * blockDim.x + threadIdx.x;
    const int n4 = NTOK * (CDIM / 4);
    if (i >= n4) return;
    int t = i / (CDIM / 4), c = i % (CDIM / 4);
    float4 a = ((const float4*)(g_y + (size_t)(2 * t) * CDIM))[c];
    float4 b = ((const float4*)(g_y + (size_t)(2 * t + 1) * CDIM))[c];
    float4 r;
    r.x = a.x + b.x;
    r.y = a.y + b.y;
    r.z = a.z + b.z;
    r.w = a.w + b.w;
    ((float4*)out)[i] = r;
}

// ---------------- launch ----------------
extern "C" void kernel_launch(void* const* d_in, const int* in_sizes, int n_in,
                              void* d_out, int out_size) {
    (void)in_sizes; (void)n_in; (void)out_size;
    const float* x  = (const float*)d_in[0];
    const float* rw = (const float*)d_in[1];
    const float* w1 = (const float*)d_in[2];
    const float* b1 = (const float*)d_in[3];
    const float* w2 = (const float*)d_in[4];
    const float* b2 = (const float*)d_in[5];
    float* out = (float*)d_out;

    cudaFuncSetAttribute(moe_gemm<1>, cudaFuncAttributeMaxDynamicSharedMemorySize, SMEM_DYN);
    cudaFuncSetAttribute(moe_gemm<2>, cudaFuncAttributeMaxDynamicSharedMemorySize, SMEM_DYN);

    init_kernel<<<1, 32>>>();
    router_kernel<<<NTOK / 8, 256>>>(x, rw);
    transpose_h<1><<<dim3(FDIM / 32, CDIM / 64, NEXP), dim3(32, 8)>>>(w1, CDIM, FDIM);
    transpose_h<2><<<dim3(CDIM / 32, FDIM / 64, NEXP), dim3(32, 8)>>>(w2, FDIM, CDIM);

    moe_gemm<1><<<dim3(NTOK / BM, FDIM / BN, NEXP), 256, SMEM_DYN>>>(b1);
    moe_gemm<2><<<dim3(NTOK / BM, CDIM / BN, NEXP), 256, SMEM_DYN>>>(b2);

    combine_kernel<<<(NTOK * (CDIM / 4) + 255) / 256, 256>>>(out);
}